// round 10
// baseline (speedup 1.0000x reference)
#include <cuda_runtime.h>
#include <cuda_fp16.h>
#include <cstdint>

// Problem constants: B=4, T=4096, C=256, H=64
#define BB 4
#define TT 4096
#define CC 256
#define HH 64
// k is pre-scaled by log2(e)/16 so softmax is a bare ex2 of the mma result.
#define KSCALE 0.09016844005556021f

// Scratch: fp16 projections (+ transposed V) + split-s partial outputs.
__device__ __half g_k[BB * TT * HH];
__device__ __half g_q[BB * TT * HH];
__device__ __half g_v[BB * TT * HH];
__device__ __half g_vt[BB * HH * TT];         // [b][h][t]
__device__ float  g_opart[2 * BB * TT * HH];  // 8MB
__device__ float  g_lpart[2 * BB * TT];
__device__ float  g_wt[192 * CC];             // W^T combined [h'][c], tf32
__device__ float  g_bias[192];

__device__ __forceinline__ uint32_t f2tf32(float f) {
    uint32_t r; asm("cvt.rna.tf32.f32 %0, %1;" : "=r"(r) : "f"(f)); return r;
}
__device__ __forceinline__ uint32_t pack_h2(float lo, float hi) {
    uint32_t r;
    asm("cvt.rn.f16x2.f32 %0, %1, %2;" : "=r"(r) : "f"(hi), "f"(lo));
    return r;
}
__device__ __forceinline__ uint32_t h2exp2(uint32_t x) {
    uint32_t r;
    asm("ex2.approx.f16x2 %0, %1;" : "=r"(r) : "r"(x));
    return r;
}
__device__ __forceinline__ uint32_t smem_u32(const void* p) {
    uint32_t a;
    asm("{ .reg .u64 t; cvta.to.shared.u64 t, %1; cvt.u32.u64 %0, t; }" : "=r"(a) : "l"(p));
    return a;
}
__device__ __forceinline__ void cp_async16(uint32_t dst, const void* src) {
    asm volatile("cp.async.cg.shared.global [%0], [%1], 16;"
                 :: "r"(dst), "l"(src) : "memory");
}
#define CP_COMMIT() asm volatile("cp.async.commit_group;" ::: "memory")
#define CP_WAIT0()  asm volatile("cp.async.wait_group 0;" ::: "memory")
#define CP_WAIT1()  asm volatile("cp.async.wait_group 1;" ::: "memory")
#define CP_WAIT2()  asm volatile("cp.async.wait_group 2;" ::: "memory")

__device__ __forceinline__ void ldmx4(uint32_t* r, uint32_t addr) {
    asm volatile("ldmatrix.sync.aligned.m8n8.x4.shared.b16 {%0,%1,%2,%3}, [%4];"
                 : "=r"(r[0]), "=r"(r[1]), "=r"(r[2]), "=r"(r[3]) : "r"(addr)
                 : "memory");
}

// tf32 m16n8k8 (used by QKV GEMM)
__device__ __forceinline__ void mma_tf32(float* c, const uint32_t* a,
                                         uint32_t b0, uint32_t b1) {
    asm volatile(
        "mma.sync.aligned.m16n8k8.row.col.f32.tf32.tf32.f32 "
        "{%0,%1,%2,%3}, {%4,%5,%6,%7}, {%8,%9}, {%0,%1,%2,%3};"
        : "+f"(c[0]), "+f"(c[1]), "+f"(c[2]), "+f"(c[3])
        : "r"(a[0]), "r"(a[1]), "r"(a[2]), "r"(a[3]), "r"(b0), "r"(b1));
}
// fp16 m16n8k16 with fp32 accum (attention). Non-volatile: schedulable.
__device__ __forceinline__ void mma_f16(float* c, const uint32_t* a,
                                        uint32_t b0, uint32_t b1) {
    asm("mma.sync.aligned.m16n8k16.row.col.f32.f16.f16.f32 "
        "{%0,%1,%2,%3}, {%4,%5,%6,%7}, {%8,%9}, {%0,%1,%2,%3};"
        : "+f"(c[0]), "+f"(c[1]), "+f"(c[2]), "+f"(c[3])
        : "r"(a[0]), "r"(a[1]), "r"(a[2]), "r"(a[3]), "r"(b0), "r"(b1));
}

// ---------------------------------------------------------------------------
// Kernel 0: build W^T [192][256] (tf32-RNA) + combined bias.
// ---------------------------------------------------------------------------
__global__ void __launch_bounds__(256) wprep_kernel(
    const float* __restrict__ Wk, const float* __restrict__ bk,
    const float* __restrict__ Wq, const float* __restrict__ bq,
    const float* __restrict__ Wv, const float* __restrict__ bv)
{
    const int j = blockIdx.x;
    const int m = j >> 6;
    const int h = j & 63;
    const int c = threadIdx.x;
    const float* W = (m == 0) ? Wk : ((m == 1) ? Wq : Wv);
    g_wt[j * CC + c] = __uint_as_float(f2tf32(W[c * HH + h]));
    if (c == 0) {
        const float* bi = (m == 0) ? bk : ((m == 1) ? bq : bv);
        g_bias[j] = bi[h];
    }
}

// ---------------------------------------------------------------------------
// Kernel 1: QKV projection as tf32 GEMM [16384,256]x[256,192]; fp16 outputs.
// ---------------------------------------------------------------------------
#define XSTR 68
#define WSTR 68
#define QKV_SMEM_BYTES ((128 * XSTR + 192 * WSTR) * 4)   // 87040

__global__ void __launch_bounds__(512, 1) qkv_mma_kernel(const float* __restrict__ x)
{
    extern __shared__ float sm[];
    float* xs = sm;
    float* ws = sm + 128 * XSTR;

    const int tid  = threadIdx.x;
    const int warp = tid >> 5;
    const int lane = tid & 31;
    const int wr = warp & 3;
    const int wc = warp >> 2;
    const int g  = lane >> 2;
    const int t4 = lane & 3;
    const int row0 = blockIdx.x * 128;

    float c[2][6][4];
    #pragma unroll
    for (int mi = 0; mi < 2; mi++)
        #pragma unroll
        for (int ni = 0; ni < 6; ni++)
            #pragma unroll
            for (int e = 0; e < 4; e++) c[mi][ni][e] = 0.0f;

    const float4* x4  = (const float4*)x;
    const float4* wt4 = (const float4*)g_wt;
    const int arow = wr * 32 + g;

    #pragma unroll
    for (int kc = 0; kc < 4; kc++) {
        __syncthreads();
        #pragma unroll
        for (int it = 0; it < 4; it++) {
            int i = tid + it * 512;
            int row = i >> 4, c4 = i & 15;
            float4 v = x4[(size_t)(row0 + row) * (CC / 4) + kc * 16 + c4];
            v.x = __uint_as_float(f2tf32(v.x));
            v.y = __uint_as_float(f2tf32(v.y));
            v.z = __uint_as_float(f2tf32(v.z));
            v.w = __uint_as_float(f2tf32(v.w));
            *(float4*)&xs[row * XSTR + c4 * 4] = v;
        }
        #pragma unroll
        for (int it = 0; it < 6; it++) {
            int i = tid + it * 512;
            int j = i >> 4, c4 = i & 15;
            *(float4*)&ws[j * WSTR + c4 * 4] = wt4[j * (CC / 4) + kc * 16 + c4];
        }
        __syncthreads();

        #pragma unroll
        for (int k8 = 0; k8 < 8; k8++) {
            const int k0 = k8 * 8;
            uint32_t a[2][4];
            #pragma unroll
            for (int mi = 0; mi < 2; mi++) {
                const float* base = &xs[(arow + mi * 16) * XSTR + k0 + t4];
                a[mi][0] = __float_as_uint(base[0]);
                a[mi][1] = __float_as_uint(base[8 * XSTR]);
                a[mi][2] = __float_as_uint(base[4]);
                a[mi][3] = __float_as_uint(base[8 * XSTR + 4]);
            }
            #pragma unroll
            for (int ni = 0; ni < 6; ni++) {
                const float* wp = &ws[(wc * 48 + ni * 8 + g) * WSTR + k0 + t4];
                const uint32_t b0 = __float_as_uint(wp[0]);
                const uint32_t b1 = __float_as_uint(wp[4]);
                mma_tf32(c[0][ni], a[0], b0, b1);
                mma_tf32(c[1][ni], a[1], b0, b1);
            }
        }
    }

    #pragma unroll
    for (int ni = 0; ni < 6; ni++) {
        const int col0 = wc * 48 + ni * 8;
        const int m = col0 >> 6;
        __half* dst = (m == 0) ? g_k : ((m == 1) ? g_q : g_v);
        const float sc = (m == 0) ? KSCALE : 1.0f;
        const int h = (col0 & 63) + 2 * t4;
        const float b0 = g_bias[col0 + 2 * t4];
        const float b1 = g_bias[col0 + 2 * t4 + 1];
        #pragma unroll
        for (int mi = 0; mi < 2; mi++) {
            const int row = row0 + wr * 32 + mi * 16 + g;
            *(uint32_t*)&dst[(size_t)row * HH + h] =
                pack_h2((c[mi][ni][0] + b0) * sc, (c[mi][ni][1] + b1) * sc);
            *(uint32_t*)&dst[(size_t)(row + 8) * HH + h] =
                pack_h2((c[mi][ni][2] + b0) * sc, (c[mi][ni][3] + b1) * sc);
        }
    }
}

// ---------------------------------------------------------------------------
// Kernel 1b: transpose V -> g_vt[b][h][t]
// ---------------------------------------------------------------------------
__global__ void __launch_bounds__(256) vtrans_kernel()
{
    __shared__ __half ts[64][66];
    const int b  = blockIdx.y;
    const int s0 = blockIdx.x * 64;
    const int tid = threadIdx.x;

    const uint32_t* src = (const uint32_t*)(g_v + ((size_t)b * TT + s0) * HH);
    #pragma unroll
    for (int it = 0; it < 8; it++) {
        int i = tid + it * 256;
        int row = i >> 5, c = i & 31;
        *(uint32_t*)&ts[row][c * 2] = src[row * 32 + c];
    }
    __syncthreads();

    const int h = tid >> 2, sq = tid & 3;
    uint32_t* dst = (uint32_t*)(g_vt + ((size_t)b * HH + h) * TT + s0);
    #pragma unroll
    for (int j = 0; j < 8; j++) {
        int s = sq * 16 + 2 * j;
        uint32_t u = ((uint32_t)__half_as_ushort(ts[s + 1][h]) << 16)
                   | (uint32_t)__half_as_ushort(ts[s][h]);
        dst[sq * 8 + j] = u;
    }
}

// ---------------------------------------------------------------------------
// Kernel 2: fp16 mma flash attention v6 — software-pipelined phases.
//  Per iteration t: MMA1(tile t+1) + exp(t+1) interleaved with MMA2(tile t),
//  so the tensor pipe stays fed during softmax. P double-buffered in regs.
//  ldmatrix.x4; ones-column row sums; 4-stage cp.async; one sync per tile.
// ---------------------------------------------------------------------------
#define QSTRH 72                      // halves per smem row (Q and Vt)
#define STAGE_H (64 * QSTRH * 2)      // one stage: Q tile + V tile (halves)
#define Q_HOFF(buf) ((buf) * STAGE_H)
#define V_HOFF(buf) ((buf) * STAGE_H + 64 * QSTRH)
#define ATTN_SMEM_BYTES (4 * STAGE_H * 2)   // 73728

__global__ void __launch_bounds__(256, 2) attn_kernel()
{
    extern __shared__ __half smh[];
    const uint32_t sbase = smem_u32(smh);

    const int tid  = threadIdx.x;
    const int warp = tid >> 5;
    const int lane = tid & 31;
    const int g  = lane >> 2;
    const int t4 = lane & 3;
    const int b  = blockIdx.y;
    const int t0 = blockIdx.x * 128;
    const int z  = blockIdx.z;

    const __half* qb  = g_q  + (size_t)b * TT * HH;
    const __half* vtb = g_vt + (size_t)b * HH * TT;

    auto issue_tile = [&](int tile, int buf) {
        const int s0 = (z * 32 + tile) * 64;
        #pragma unroll
        for (int it = 0; it < 2; it++) {
            int i = tid + it * 256;          // 0..511
            int row = i >> 3, c8 = i & 7;
            cp_async16(sbase + (Q_HOFF(buf) + row * QSTRH + c8 * 8) * 2,
                       qb + (size_t)(s0 + row) * HH + c8 * 8);
            cp_async16(sbase + (V_HOFF(buf) + row * QSTRH + c8 * 8) * 2,
                       vtb + (size_t)row * TT + s0 + c8 * 8);
        }
        CP_COMMIT();
    };

    issue_tile(0, 0);
    issue_tile(1, 1);
    issue_tile(2, 2);

    // --- K fragments (fp16) to registers: warp owns rows [warp*16, +16) ---
    uint32_t kf[4][4];
    {
        const __half* kbp = g_k + ((size_t)(b * TT) + t0 + warp * 16) * HH;
        #pragma unroll
        for (int kb = 0; kb < 4; kb++) {
            const int k0 = kb * 16 + 2 * t4;
            kf[kb][0] = *(const uint32_t*)&kbp[(size_t)g * HH + k0];
            kf[kb][1] = *(const uint32_t*)&kbp[(size_t)(g + 8) * HH + k0];
            kf[kb][2] = *(const uint32_t*)&kbp[(size_t)g * HH + k0 + 8];
            kf[kb][3] = *(const uint32_t*)&kbp[(size_t)(g + 8) * HH + k0 + 8];
        }
    }

    float o[8][4];
    #pragma unroll
    for (int nj = 0; nj < 8; nj++)
        #pragma unroll
        for (int e = 0; e < 4; e++) o[nj][e] = 0.0f;
    float ol[4] = {0.f, 0.f, 0.f, 0.f};           // ones-column: row sums
    const uint32_t ones = (g == 0) ? 0x3C003C00u : 0u;

    // ldmatrix per-lane byte offset
    const uint32_t lmlane =
        ((((lane >> 4) & 1) * 8 + (lane & 7)) * QSTRH) * 2 + ((lane >> 3) & 1) * 16;

    uint32_t paA[4][4], paB[4][4];

    // ---- prologue: MMA1 + exp for tile 0 -> paA ----
    CP_WAIT2();
    __syncthreads();
    {
        const uint32_t qbase = sbase + Q_HOFF(0) * 2 + lmlane;
        #pragma unroll
        for (int nh = 0; nh < 2; nh++) {
            float c[4][4];
            #pragma unroll
            for (int j = 0; j < 4; j++)
                #pragma unroll
                for (int e = 0; e < 4; e++) c[j][e] = 0.0f;
            #pragma unroll
            for (int kb = 0; kb < 4; kb++) {
                uint32_t q0[4], q1[4];
                ldmx4(q0, qbase + (2 * nh)     * (16 * QSTRH * 2) + kb * 32);
                ldmx4(q1, qbase + (2 * nh + 1) * (16 * QSTRH * 2) + kb * 32);
                mma_f16(c[0], kf[kb], q0[0], q0[1]);
                mma_f16(c[1], kf[kb], q0[2], q0[3]);
                mma_f16(c[2], kf[kb], q1[0], q1[1]);
                mma_f16(c[3], kf[kb], q1[2], q1[3]);
            }
            #pragma unroll
            for (int j = 0; j < 4; j++) {
                const int ni = nh * 4 + j;
                paA[ni >> 1][(ni & 1) * 2 + 0] = h2exp2(pack_h2(c[j][0], c[j][1]));
                paA[ni >> 1][(ni & 1) * 2 + 1] = h2exp2(pack_h2(c[j][2], c[j][3]));
            }
        }
    }

    // ---- pipelined body: MMA2(t) with pin; MMA1+exp(t+1) -> pout ----
    auto body = [&](int t, uint32_t (&pin)[4][4], uint32_t (&pout)[4][4]) {
        if (t >= 30) { CP_WAIT0(); } else { CP_WAIT1(); }
        __syncthreads();
        if (t + 3 < 32) issue_tile(t + 3, (t + 3) & 3);

        const uint32_t vbase = sbase + V_HOFF(t & 3) * 2 + lmlane;
        const uint32_t qbase = sbase + Q_HOFF((t + 1) & 3) * 2 + lmlane;
        const bool notlast = (t < 31);

        #pragma unroll
        for (int nh = 0; nh < 2; nh++) {
            float c[4][4];
            #pragma unroll
            for (int j = 0; j < 4; j++)
                #pragma unroll
                for (int e = 0; e < 4; e++) c[j][e] = 0.0f;

            if (notlast) {
                #pragma unroll
                for (int kb = 0; kb < 4; kb++) {
                    uint32_t q0[4], q1[4];
                    ldmx4(q0, qbase + (2 * nh)     * (16 * QSTRH * 2) + kb * 32);
                    ldmx4(q1, qbase + (2 * nh + 1) * (16 * QSTRH * 2) + kb * 32);
                    mma_f16(c[0], kf[kb], q0[0], q0[1]);
                    mma_f16(c[1], kf[kb], q0[2], q0[3]);
                    mma_f16(c[2], kf[kb], q1[0], q1[1]);
                    mma_f16(c[3], kf[kb], q1[2], q1[3]);
                }
            }
            // MMA2 half: kb = 2*nh, 2*nh+1 on tile t (uses pin, independent)
            #pragma unroll
            for (int kk = 0; kk < 2; kk++) {
                const int kb = 2 * nh + kk;
                #pragma unroll
                for (int m = 0; m < 4; m++) {
                    uint32_t vf[4];
                    ldmx4(vf, vbase + m * (16 * QSTRH * 2) + kb * 32);
                    mma_f16(o[2 * m],     pin[kb], vf[0], vf[1]);
                    mma_f16(o[2 * m + 1], pin[kb], vf[2], vf[3]);
                }
                mma_f16(ol, pin[kb], ones, ones);
            }
            if (notlast) {
                #pragma unroll
                for (int j = 0; j < 4; j++) {
                    const int ni = nh * 4 + j;
                    pout[ni >> 1][(ni & 1) * 2 + 0] = h2exp2(pack_h2(c[j][0], c[j][1]));
                    pout[ni >> 1][(ni & 1) * 2 + 1] = h2exp2(pack_h2(c[j][2], c[j][3]));
                }
            }
        }
    };

    for (int t = 0; t < 32; t += 2) {
        body(t,     paA, paB);
        body(t + 1, paB, paA);
    }

    // ---- epilogue: row sums from ones-column; partial O to scratch ----
    const int row = t0 + warp * 16 + g;
    if (t4 == 0) {
        g_lpart[z * (BB * TT) + b * TT + row]     = ol[0];
        g_lpart[z * (BB * TT) + b * TT + row + 8] = ol[2];
    }
    float* ob = g_opart + (size_t)z * (BB * TT * HH) + (size_t)(b * TT + row) * HH;
    #pragma unroll
    for (int nj = 0; nj < 8; nj++) {
        const int col = nj * 8 + 2 * t4;
        *(float2*)&ob[col]          = make_float2(o[nj][0], o[nj][1]);
        *(float2*)&ob[8 * HH + col] = make_float2(o[nj][2], o[nj][3]);
    }
}

// ---------------------------------------------------------------------------
// Kernel 3: combine the two s-splits and normalize.
// ---------------------------------------------------------------------------
__global__ void __launch_bounds__(256) combine_kernel(float* __restrict__ out)
{
    const int i4 = blockIdx.x * 256 + threadIdx.x;
    const int row = i4 >> 4;
    const float inv = 1.0f / (g_lpart[row] + g_lpart[BB * TT + row]);
    const float4 a = ((const float4*)g_opart)[i4];
    const float4 c = ((const float4*)(g_opart + (size_t)BB * TT * HH))[i4];
    float4 r;
    r.x = (a.x + c.x) * inv;
    r.y = (a.y + c.y) * inv;
    r.z = (a.z + c.z) * inv;
    r.w = (a.w + c.w) * inv;
    ((float4*)out)[i4] = r;
}

// ---------------------------------------------------------------------------
extern "C" void kernel_launch(void* const* d_in, const int* in_sizes, int n_in,
                              void* d_out, int out_size)
{
    const float* x  = (const float*)d_in[0];
    const float* Wk = (const float*)d_in[1];
    const float* bk = (const float*)d_in[2];
    const float* Wq = (const float*)d_in[3];
    const float* bq = (const float*)d_in[4];
    const float* Wv = (const float*)d_in[5];
    const float* bv = (const float*)d_in[6];
    float* out = (float*)d_out;

    cudaFuncSetAttribute(qkv_mma_kernel, cudaFuncAttributeMaxDynamicSharedMemorySize,
                         QKV_SMEM_BYTES);
    cudaFuncSetAttribute(attn_kernel, cudaFuncAttributeMaxDynamicSharedMemorySize,
                         ATTN_SMEM_BYTES);

    wprep_kernel<<<192, 256>>>(Wk, bk, Wq, bq, Wv, bv);
    qkv_mma_kernel<<<(BB * TT) / 128, 512, QKV_SMEM_BYTES>>>(x);

    dim3 tgrid(TT / 64, BB);
    vtrans_kernel<<<tgrid, 256>>>();

    dim3 grid(TT / 128, BB, 2);
    attn_kernel<<<grid, 256, ATTN_SMEM_BYTES>>>();

    combine_kernel<<<(BB * TT * HH) / (4 * 256), 256>>>(out);
}

// round 11
// speedup vs baseline: 1.0251x; 1.0251x over previous
#include <cuda_runtime.h>
#include <cuda_fp16.h>
#include <cstdint>

// Problem constants: B=4, T=4096, C=256, H=64
#define BB 4
#define TT 4096
#define CC 256
#define HH 64
// k is pre-scaled by log2(e)/16 so softmax is a bare ex2 of the mma result.
#define KSCALE 0.09016844005556021f

// Scratch: fp16 projections (+ transposed V) + split-s partial outputs.
__device__ __half g_k[BB * TT * HH];
__device__ __half g_q[BB * TT * HH];
__device__ __half g_v[BB * TT * HH];
__device__ __half g_vt[BB * HH * TT];         // [b][h][t]
__device__ float  g_opart[2 * BB * TT * HH];  // 8MB
__device__ float  g_lpart[2 * BB * TT];
__device__ float  g_wt[192 * CC];             // W^T combined [h'][c], tf32
__device__ float  g_bias[192];

__device__ __forceinline__ uint32_t f2tf32(float f) {
    uint32_t r; asm("cvt.rna.tf32.f32 %0, %1;" : "=r"(r) : "f"(f)); return r;
}
__device__ __forceinline__ uint32_t pack_h2(float lo, float hi) {
    uint32_t r;
    asm("cvt.rn.f16x2.f32 %0, %1, %2;" : "=r"(r) : "f"(hi), "f"(lo));
    return r;
}
__device__ __forceinline__ uint32_t h2exp2(uint32_t x) {
    uint32_t r;
    asm("ex2.approx.f16x2 %0, %1;" : "=r"(r) : "r"(x));
    return r;
}
__device__ __forceinline__ uint32_t smem_u32(const void* p) {
    uint32_t a;
    asm("{ .reg .u64 t; cvta.to.shared.u64 t, %1; cvt.u32.u64 %0, t; }" : "=r"(a) : "l"(p));
    return a;
}
__device__ __forceinline__ void cp_async16(uint32_t dst, const void* src) {
    asm volatile("cp.async.cg.shared.global [%0], [%1], 16;"
                 :: "r"(dst), "l"(src) : "memory");
}
#define CP_COMMIT() asm volatile("cp.async.commit_group;" ::: "memory")
#define CP_WAIT0()  asm volatile("cp.async.wait_group 0;" ::: "memory")
#define CP_WAIT1()  asm volatile("cp.async.wait_group 1;" ::: "memory")

__device__ __forceinline__ void ldmx4(uint32_t* r, uint32_t addr) {
    asm volatile("ldmatrix.sync.aligned.m8n8.x4.shared.b16 {%0,%1,%2,%3}, [%4];"
                 : "=r"(r[0]), "=r"(r[1]), "=r"(r[2]), "=r"(r[3]) : "r"(addr)
                 : "memory");
}

// tf32 m16n8k8 (used by QKV GEMM)
__device__ __forceinline__ void mma_tf32(float* c, const uint32_t* a,
                                         uint32_t b0, uint32_t b1) {
    asm volatile(
        "mma.sync.aligned.m16n8k8.row.col.f32.tf32.tf32.f32 "
        "{%0,%1,%2,%3}, {%4,%5,%6,%7}, {%8,%9}, {%0,%1,%2,%3};"
        : "+f"(c[0]), "+f"(c[1]), "+f"(c[2]), "+f"(c[3])
        : "r"(a[0]), "r"(a[1]), "r"(a[2]), "r"(a[3]), "r"(b0), "r"(b1));
}
// fp16 m16n8k16 with fp32 accum (attention). Non-volatile: schedulable.
__device__ __forceinline__ void mma_f16(float* c, const uint32_t* a,
                                        uint32_t b0, uint32_t b1) {
    asm("mma.sync.aligned.m16n8k16.row.col.f32.f16.f16.f32 "
        "{%0,%1,%2,%3}, {%4,%5,%6,%7}, {%8,%9}, {%0,%1,%2,%3};"
        : "+f"(c[0]), "+f"(c[1]), "+f"(c[2]), "+f"(c[3])
        : "r"(a[0]), "r"(a[1]), "r"(a[2]), "r"(a[3]), "r"(b0), "r"(b1));
}

// ---------------------------------------------------------------------------
// Kernel 0: build W^T [192][256] (tf32-RNA) + combined bias.
// ---------------------------------------------------------------------------
__global__ void __launch_bounds__(256) wprep_kernel(
    const float* __restrict__ Wk, const float* __restrict__ bk,
    const float* __restrict__ Wq, const float* __restrict__ bq,
    const float* __restrict__ Wv, const float* __restrict__ bv)
{
    const int j = blockIdx.x;
    const int m = j >> 6;
    const int h = j & 63;
    const int c = threadIdx.x;
    const float* W = (m == 0) ? Wk : ((m == 1) ? Wq : Wv);
    g_wt[j * CC + c] = __uint_as_float(f2tf32(W[c * HH + h]));
    if (c == 0) {
        const float* bi = (m == 0) ? bk : ((m == 1) ? bq : bv);
        g_bias[j] = bi[h];
    }
}

// ---------------------------------------------------------------------------
// Kernel 1: QKV projection as tf32 GEMM [16384,256]x[256,192]; fp16 outputs.
// ---------------------------------------------------------------------------
#define XSTR 68
#define WSTR 68
#define QKV_SMEM_BYTES ((128 * XSTR + 192 * WSTR) * 4)   // 87040

__global__ void __launch_bounds__(512, 1) qkv_mma_kernel(const float* __restrict__ x)
{
    extern __shared__ float sm[];
    float* xs = sm;
    float* ws = sm + 128 * XSTR;

    const int tid  = threadIdx.x;
    const int warp = tid >> 5;
    const int lane = tid & 31;
    const int wr = warp & 3;
    const int wc = warp >> 2;
    const int g  = lane >> 2;
    const int t4 = lane & 3;
    const int row0 = blockIdx.x * 128;

    float c[2][6][4];
    #pragma unroll
    for (int mi = 0; mi < 2; mi++)
        #pragma unroll
        for (int ni = 0; ni < 6; ni++)
            #pragma unroll
            for (int e = 0; e < 4; e++) c[mi][ni][e] = 0.0f;

    const float4* x4  = (const float4*)x;
    const float4* wt4 = (const float4*)g_wt;
    const int arow = wr * 32 + g;

    #pragma unroll
    for (int kc = 0; kc < 4; kc++) {
        __syncthreads();
        #pragma unroll
        for (int it = 0; it < 4; it++) {
            int i = tid + it * 512;
            int row = i >> 4, c4 = i & 15;
            float4 v = x4[(size_t)(row0 + row) * (CC / 4) + kc * 16 + c4];
            v.x = __uint_as_float(f2tf32(v.x));
            v.y = __uint_as_float(f2tf32(v.y));
            v.z = __uint_as_float(f2tf32(v.z));
            v.w = __uint_as_float(f2tf32(v.w));
            *(float4*)&xs[row * XSTR + c4 * 4] = v;
        }
        #pragma unroll
        for (int it = 0; it < 6; it++) {
            int i = tid + it * 512;
            int j = i >> 4, c4 = i & 15;
            *(float4*)&ws[j * WSTR + c4 * 4] = wt4[j * (CC / 4) + kc * 16 + c4];
        }
        __syncthreads();

        #pragma unroll
        for (int k8 = 0; k8 < 8; k8++) {
            const int k0 = k8 * 8;
            uint32_t a[2][4];
            #pragma unroll
            for (int mi = 0; mi < 2; mi++) {
                const float* base = &xs[(arow + mi * 16) * XSTR + k0 + t4];
                a[mi][0] = __float_as_uint(base[0]);
                a[mi][1] = __float_as_uint(base[8 * XSTR]);
                a[mi][2] = __float_as_uint(base[4]);
                a[mi][3] = __float_as_uint(base[8 * XSTR + 4]);
            }
            #pragma unroll
            for (int ni = 0; ni < 6; ni++) {
                const float* wp = &ws[(wc * 48 + ni * 8 + g) * WSTR + k0 + t4];
                const uint32_t b0 = __float_as_uint(wp[0]);
                const uint32_t b1 = __float_as_uint(wp[4]);
                mma_tf32(c[0][ni], a[0], b0, b1);
                mma_tf32(c[1][ni], a[1], b0, b1);
            }
        }
    }

    #pragma unroll
    for (int ni = 0; ni < 6; ni++) {
        const int col0 = wc * 48 + ni * 8;
        const int m = col0 >> 6;
        __half* dst = (m == 0) ? g_k : ((m == 1) ? g_q : g_v);
        const float sc = (m == 0) ? KSCALE : 1.0f;
        const int h = (col0 & 63) + 2 * t4;
        const float b0 = g_bias[col0 + 2 * t4];
        const float b1 = g_bias[col0 + 2 * t4 + 1];
        #pragma unroll
        for (int mi = 0; mi < 2; mi++) {
            const int row = row0 + wr * 32 + mi * 16 + g;
            *(uint32_t*)&dst[(size_t)row * HH + h] =
                pack_h2((c[mi][ni][0] + b0) * sc, (c[mi][ni][1] + b1) * sc);
            *(uint32_t*)&dst[(size_t)(row + 8) * HH + h] =
                pack_h2((c[mi][ni][2] + b0) * sc, (c[mi][ni][3] + b1) * sc);
        }
    }
}

// ---------------------------------------------------------------------------
// Kernel 1b: transpose V -> g_vt[b][h][t]
// ---------------------------------------------------------------------------
__global__ void __launch_bounds__(256) vtrans_kernel()
{
    __shared__ __half ts[64][66];
    const int b  = blockIdx.y;
    const int s0 = blockIdx.x * 64;
    const int tid = threadIdx.x;

    const uint32_t* src = (const uint32_t*)(g_v + ((size_t)b * TT + s0) * HH);
    #pragma unroll
    for (int it = 0; it < 8; it++) {
        int i = tid + it * 256;
        int row = i >> 5, c = i & 31;
        *(uint32_t*)&ts[row][c * 2] = src[row * 32 + c];
    }
    __syncthreads();

    const int h = tid >> 2, sq = tid & 3;
    uint32_t* dst = (uint32_t*)(g_vt + ((size_t)b * HH + h) * TT + s0);
    #pragma unroll
    for (int j = 0; j < 8; j++) {
        int s = sq * 16 + 2 * j;
        uint32_t u = ((uint32_t)__half_as_ushort(ts[s + 1][h]) << 16)
                   | (uint32_t)__half_as_ushort(ts[s][h]);
        dst[sq * 8 + j] = u;
    }
}

// ---------------------------------------------------------------------------
// Kernel 2: fp16 mma flash attention v7 — small CTAs for cross-CTA overlap.
//  128-thr CTA (4 warps x 16 t-rows = 64 rows), 3-stage cp.async (55KB smem),
//  4 CTA/SM: barrier scope is 4 warps; co-resident CTAs run phase-shifted so
//  the tensor pipe is fed during softmax. Loop body identical to R9 (best).
// ---------------------------------------------------------------------------
#define QSTRH 72                      // halves per smem row (Q and Vt)
#define STAGE_H (64 * QSTRH * 2)      // one stage: Q tile + V tile (halves)
#define Q_HOFF(buf) ((buf) * STAGE_H)
#define V_HOFF(buf) ((buf) * STAGE_H + 64 * QSTRH)
#define ATTN_SMEM_BYTES (3 * STAGE_H * 2)   // 55296

__global__ void __launch_bounds__(128, 4) attn_kernel()
{
    extern __shared__ __half smh[];
    const uint32_t sbase = smem_u32(smh);

    const int tid  = threadIdx.x;
    const int warp = tid >> 5;
    const int lane = tid & 31;
    const int g  = lane >> 2;
    const int t4 = lane & 3;
    const int b  = blockIdx.y;
    const int t0 = blockIdx.x * 64;
    const int z  = blockIdx.z;

    const __half* qb  = g_q  + (size_t)b * TT * HH;
    const __half* vtb = g_vt + (size_t)b * HH * TT;

    auto issue_tile = [&](int tile, int buf) {
        const int s0 = (z * 32 + tile) * 64;
        #pragma unroll
        for (int it = 0; it < 4; it++) {
            int i = tid + it * 128;          // 0..511
            int row = i >> 3, c8 = i & 7;
            cp_async16(sbase + (Q_HOFF(buf) + row * QSTRH + c8 * 8) * 2,
                       qb + (size_t)(s0 + row) * HH + c8 * 8);
            cp_async16(sbase + (V_HOFF(buf) + row * QSTRH + c8 * 8) * 2,
                       vtb + (size_t)row * TT + s0 + c8 * 8);
        }
        CP_COMMIT();
    };

    issue_tile(0, 0);
    issue_tile(1, 1);

    // --- K fragments (fp16) to registers: warp owns rows [warp*16, +16) ---
    uint32_t kf[4][4];
    {
        const __half* kbp = g_k + ((size_t)(b * TT) + t0 + warp * 16) * HH;
        #pragma unroll
        for (int kb = 0; kb < 4; kb++) {
            const int k0 = kb * 16 + 2 * t4;
            kf[kb][0] = *(const uint32_t*)&kbp[(size_t)g * HH + k0];
            kf[kb][1] = *(const uint32_t*)&kbp[(size_t)(g + 8) * HH + k0];
            kf[kb][2] = *(const uint32_t*)&kbp[(size_t)g * HH + k0 + 8];
            kf[kb][3] = *(const uint32_t*)&kbp[(size_t)(g + 8) * HH + k0 + 8];
        }
    }

    float o[8][4];
    #pragma unroll
    for (int nj = 0; nj < 8; nj++)
        #pragma unroll
        for (int e = 0; e < 4; e++) o[nj][e] = 0.0f;
    float ol[4] = {0.f, 0.f, 0.f, 0.f};           // ones-column: row sums
    const uint32_t ones = (g == 0) ? 0x3C003C00u : 0u;

    // ldmatrix per-lane byte offset
    const uint32_t lmlane =
        ((((lane >> 4) & 1) * 8 + (lane & 7)) * QSTRH) * 2 + ((lane >> 3) & 1) * 16;

    for (int tile = 0; tile < 32; tile++) {
        const int buf = tile % 3;
        if (tile >= 30) { CP_WAIT0(); } else { CP_WAIT1(); }
        __syncthreads();
        if (tile + 2 < 32) issue_tile(tile + 2, (tile + 2) % 3);

        const uint32_t qbase = sbase + Q_HOFF(buf) * 2 + lmlane;
        const uint32_t vbase = sbase + V_HOFF(buf) * 2 + lmlane;

        // ---- MMA1 + softmax in two ni-halves; P packs into MMA2 A-frags ----
        uint32_t pa[4][4];
        #pragma unroll
        for (int nh = 0; nh < 2; nh++) {
            float c[4][4];
            #pragma unroll
            for (int j = 0; j < 4; j++)
                #pragma unroll
                for (int e = 0; e < 4; e++) c[j][e] = 0.0f;

            #pragma unroll
            for (int kb = 0; kb < 4; kb++) {
                uint32_t q0[4], q1[4];
                ldmx4(q0, qbase + (2 * nh)     * (16 * QSTRH * 2) + kb * 32);
                ldmx4(q1, qbase + (2 * nh + 1) * (16 * QSTRH * 2) + kb * 32);
                mma_f16(c[0], kf[kb], q0[0], q0[1]);
                mma_f16(c[1], kf[kb], q0[2], q0[3]);
                mma_f16(c[2], kf[kb], q1[0], q1[1]);
                mma_f16(c[3], kf[kb], q1[2], q1[3]);
            }
            // pack logits to f16x2, then one MUFU per pair
            #pragma unroll
            for (int j = 0; j < 4; j++) {
                const int ni = nh * 4 + j;
                pa[ni >> 1][(ni & 1) * 2 + 0] = h2exp2(pack_h2(c[j][0], c[j][1]));
                pa[ni >> 1][(ni & 1) * 2 + 1] = h2exp2(pack_h2(c[j][2], c[j][3]));
            }
        }

        // ---- MMA2: O[16t x 64h] += P . V^T ; +ones column for row sums ----
        #pragma unroll
        for (int kb = 0; kb < 4; kb++) {
            #pragma unroll
            for (int m = 0; m < 4; m++) {
                uint32_t vf[4];
                ldmx4(vf, vbase + m * (16 * QSTRH * 2) + kb * 32);
                mma_f16(o[2 * m],     pa[kb], vf[0], vf[1]);
                mma_f16(o[2 * m + 1], pa[kb], vf[2], vf[3]);
            }
            mma_f16(ol, pa[kb], ones, ones);
        }
    }

    // ---- epilogue: row sums from ones-column; partial O to scratch ----
    const int row = t0 + warp * 16 + g;
    if (t4 == 0) {
        g_lpart[z * (BB * TT) + b * TT + row]     = ol[0];
        g_lpart[z * (BB * TT) + b * TT + row + 8] = ol[2];
    }
    float* ob = g_opart + (size_t)z * (BB * TT * HH) + (size_t)(b * TT + row) * HH;
    #pragma unroll
    for (int nj = 0; nj < 8; nj++) {
        const int col = nj * 8 + 2 * t4;
        *(float2*)&ob[col]          = make_float2(o[nj][0], o[nj][1]);
        *(float2*)&ob[8 * HH + col] = make_float2(o[nj][2], o[nj][3]);
    }
}

// ---------------------------------------------------------------------------
// Kernel 3: combine the two s-splits and normalize.
// ---------------------------------------------------------------------------
__global__ void __launch_bounds__(256) combine_kernel(float* __restrict__ out)
{
    const int i4 = blockIdx.x * 256 + threadIdx.x;
    const int row = i4 >> 4;
    const float inv = 1.0f / (g_lpart[row] + g_lpart[BB * TT + row]);
    const float4 a = ((const float4*)g_opart)[i4];
    const float4 c = ((const float4*)(g_opart + (size_t)BB * TT * HH))[i4];
    float4 r;
    r.x = (a.x + c.x) * inv;
    r.y = (a.y + c.y) * inv;
    r.z = (a.z + c.z) * inv;
    r.w = (a.w + c.w) * inv;
    ((float4*)out)[i4] = r;
}

// ---------------------------------------------------------------------------
extern "C" void kernel_launch(void* const* d_in, const int* in_sizes, int n_in,
                              void* d_out, int out_size)
{
    const float* x  = (const float*)d_in[0];
    const float* Wk = (const float*)d_in[1];
    const float* bk = (const float*)d_in[2];
    const float* Wq = (const float*)d_in[3];
    const float* bq = (const float*)d_in[4];
    const float* Wv = (const float*)d_in[5];
    const float* bv = (const float*)d_in[6];
    float* out = (float*)d_out;

    cudaFuncSetAttribute(qkv_mma_kernel, cudaFuncAttributeMaxDynamicSharedMemorySize,
                         QKV_SMEM_BYTES);
    cudaFuncSetAttribute(attn_kernel, cudaFuncAttributeMaxDynamicSharedMemorySize,
                         ATTN_SMEM_BYTES);

    wprep_kernel<<<192, 256>>>(Wk, bk, Wq, bq, Wv, bv);
    qkv_mma_kernel<<<(BB * TT) / 128, 512, QKV_SMEM_BYTES>>>(x);

    dim3 tgrid(TT / 64, BB);
    vtrans_kernel<<<tgrid, 256>>>();

    dim3 grid(TT / 64, BB, 2);
    attn_kernel<<<grid, 128, ATTN_SMEM_BYTES>>>();

    combine_kernel<<<(BB * TT * HH) / (4 * 256), 256>>>(out);
}

// round 14
// speedup vs baseline: 1.1369x; 1.1091x over previous
#include <cuda_runtime.h>
#include <cuda_fp16.h>
#include <cstdint>

// Problem constants: B=4, T=4096, C=256, H=64
#define BB 4
#define TT 4096
#define CC 256
#define HH 64
// k is pre-scaled by log2(e)/16 so softmax is a bare ex2 of the mma result.
#define KSCALE 0.09016844005556021f

// Scratch: fp16 projections (K,Q row-major; V transposed) + split-s partials.
__device__ __half g_k[BB * TT * HH];
__device__ __half g_q[BB * TT * HH];
__device__ __half g_vt[BB * HH * TT];         // [b][h][t]
__device__ float  g_opart[2 * BB * TT * HH];  // 8MB
__device__ float  g_lpart[2 * BB * TT];
__device__ __half g_wth[192 * CC];            // W^T combined [h'][c], fp16
__device__ float  g_bias[192];

__device__ __forceinline__ uint32_t pack_h2(float lo, float hi) {
    uint32_t r;
    asm("cvt.rn.f16x2.f32 %0, %1, %2;" : "=r"(r) : "f"(hi), "f"(lo));
    return r;
}
__device__ __forceinline__ uint32_t h2exp2(uint32_t x) {
    uint32_t r;
    asm("ex2.approx.f16x2 %0, %1;" : "=r"(r) : "r"(x));
    return r;
}
__device__ __forceinline__ uint32_t smem_u32(const void* p) {
    uint32_t a;
    asm("{ .reg .u64 t; cvta.to.shared.u64 t, %1; cvt.u32.u64 %0, t; }" : "=r"(a) : "l"(p));
    return a;
}
__device__ __forceinline__ void cp_async16(uint32_t dst, const void* src) {
    asm volatile("cp.async.cg.shared.global [%0], [%1], 16;"
                 :: "r"(dst), "l"(src) : "memory");
}
#define CP_COMMIT() asm volatile("cp.async.commit_group;" ::: "memory")
#define CP_WAIT0()  asm volatile("cp.async.wait_group 0;" ::: "memory")
#define CP_WAIT1()  asm volatile("cp.async.wait_group 1;" ::: "memory")

// R11-exact: volatile + memory clobber (known-good ordering).
__device__ __forceinline__ void ldmx4(uint32_t* r, uint32_t addr) {
    asm volatile("ldmatrix.sync.aligned.m8n8.x4.shared.b16 {%0,%1,%2,%3}, [%4];"
                 : "=r"(r[0]), "=r"(r[1]), "=r"(r[2]), "=r"(r[3]) : "r"(addr)
                 : "memory");
}

// fp16 m16n8k16 with fp32 accum. Non-volatile: schedulable.
__device__ __forceinline__ void mma_f16(float* c, const uint32_t* a,
                                        uint32_t b0, uint32_t b1) {
    asm("mma.sync.aligned.m16n8k16.row.col.f32.f16.f16.f32 "
        "{%0,%1,%2,%3}, {%4,%5,%6,%7}, {%8,%9}, {%0,%1,%2,%3};"
        : "+f"(c[0]), "+f"(c[1]), "+f"(c[2]), "+f"(c[3])
        : "r"(a[0]), "r"(a[1]), "r"(a[2]), "r"(a[3]), "r"(b0), "r"(b1));
}

// ---------------------------------------------------------------------------
// Kernel 0: build W^T [192][256] (fp16) + combined bias.
// ---------------------------------------------------------------------------
__global__ void __launch_bounds__(256) wprep_kernel(
    const float* __restrict__ Wk, const float* __restrict__ bk,
    const float* __restrict__ Wq, const float* __restrict__ bq,
    const float* __restrict__ Wv, const float* __restrict__ bv)
{
    const int j = blockIdx.x;
    const int m = j >> 6;
    const int h = j & 63;
    const int c = threadIdx.x;
    const float* W = (m == 0) ? Wk : ((m == 1) ? Wq : Wv);
    g_wth[j * CC + c] = __float2half_rn(W[c * HH + h]);
    if (c == 0) {
        const float* bi = (m == 0) ? bk : ((m == 1) ? bq : bv);
        g_bias[j] = bi[h];
    }
}

// ---------------------------------------------------------------------------
// Kernel 1: QKV projection as fp16 GEMM [16384,256]x[256,192].
// Outputs: g_k (scaled), g_q, and g_vt (V transposed — fused, no vtrans pass).
// ---------------------------------------------------------------------------
#define XSTRH 72
#define WSTRH 72
#define QKV_SMEM_BYTES ((128 * XSTRH + 192 * WSTRH) * 2)   // 46080

__global__ void __launch_bounds__(512, 1) qkv_mma_kernel(const float* __restrict__ x)
{
    extern __shared__ __half smq[];
    __half* xs = smq;
    __half* ws = smq + 128 * XSTRH;

    const int tid  = threadIdx.x;
    const int warp = tid >> 5;
    const int lane = tid & 31;
    const int wr = warp & 3;
    const int wc = warp >> 2;
    const int g  = lane >> 2;
    const int t4 = lane & 3;
    const int row0 = blockIdx.x * 128;

    float c[2][6][4];
    #pragma unroll
    for (int mi = 0; mi < 2; mi++)
        #pragma unroll
        for (int ni = 0; ni < 6; ni++)
            #pragma unroll
            for (int e = 0; e < 4; e++) c[mi][ni][e] = 0.0f;

    const float4* x4 = (const float4*)x;
    const int arow = wr * 32 + g;

    #pragma unroll
    for (int kc = 0; kc < 4; kc++) {
        __syncthreads();
        // stage x chunk [128][64] -> fp16 (uint2 = 4 halves at c4*4)
        #pragma unroll
        for (int it = 0; it < 4; it++) {
            int i = tid + it * 512;
            int row = i >> 4, c4 = i & 15;
            float4 v = x4[(size_t)(row0 + row) * (CC / 4) + kc * 16 + c4];
            uint2 u;
            u.x = pack_h2(v.x, v.y);
            u.y = pack_h2(v.z, v.w);
            *(uint2*)&xs[row * XSTRH + c4 * 4] = u;
        }
        // stage W^T chunk [192][64]: uint4 = 8 halves at c8*8  (R12/R13 bug
        // was uint2 here — only half the weights landed)
        #pragma unroll
        for (int it = 0; it < 3; it++) {
            int i = tid + it * 512;
            int row = i >> 3, c8 = i & 7;
            uint4 u = *(const uint4*)(g_wth + row * CC + kc * 64 + c8 * 8);
            *(uint4*)&ws[row * WSTRH + c8 * 8] = u;
        }
        __syncthreads();

        #pragma unroll
        for (int k16 = 0; k16 < 4; k16++) {
            const int k0 = k16 * 16;
            uint32_t a[2][4];
            #pragma unroll
            for (int mi = 0; mi < 2; mi++) {
                const __half* base = &xs[(arow + mi * 16) * XSTRH + k0 + 2 * t4];
                a[mi][0] = *(const uint32_t*)base;
                a[mi][1] = *(const uint32_t*)(base + 8 * XSTRH);
                a[mi][2] = *(const uint32_t*)(base + 8);
                a[mi][3] = *(const uint32_t*)(base + 8 * XSTRH + 8);
            }
            #pragma unroll
            for (int ni = 0; ni < 6; ni++) {
                const __half* wp = &ws[(wc * 48 + ni * 8 + g) * WSTRH + k0 + 2 * t4];
                const uint32_t b0 = *(const uint32_t*)wp;
                const uint32_t b1 = *(const uint32_t*)(wp + 8);
                mma_f16(c[0][ni], a[0], b0, b1);
                mma_f16(c[1][ni], a[1], b0, b1);
            }
        }
    }

    // epilogue: +bias; k scaled; k,q row-major fp16; v transposed to g_vt.
    const int bb_ = row0 / TT;
    #pragma unroll
    for (int ni = 0; ni < 6; ni++) {
        const int col0 = wc * 48 + ni * 8;
        const int m = col0 >> 6;
        const float b0 = g_bias[col0 + 2 * t4];
        const float b1 = g_bias[col0 + 2 * t4 + 1];
        if (m == 2) {
            const int h = (col0 & 63) + 2 * t4;
            __half* vt = g_vt + (size_t)bb_ * HH * TT;
            #pragma unroll
            for (int mi = 0; mi < 2; mi++) {
                const int t = (row0 - bb_ * TT) + wr * 32 + mi * 16 + g;
                vt[(size_t)h * TT + t]           = __float2half_rn(c[mi][ni][0] + b0);
                vt[(size_t)(h + 1) * TT + t]     = __float2half_rn(c[mi][ni][1] + b1);
                vt[(size_t)h * TT + t + 8]       = __float2half_rn(c[mi][ni][2] + b0);
                vt[(size_t)(h + 1) * TT + t + 8] = __float2half_rn(c[mi][ni][3] + b1);
            }
        } else {
            __half* dst = (m == 0) ? g_k : g_q;
            const float sc = (m == 0) ? KSCALE : 1.0f;
            const int h = (col0 & 63) + 2 * t4;
            #pragma unroll
            for (int mi = 0; mi < 2; mi++) {
                const int row = row0 + wr * 32 + mi * 16 + g;
                *(uint32_t*)&dst[(size_t)row * HH + h] =
                    pack_h2((c[mi][ni][0] + b0) * sc, (c[mi][ni][1] + b1) * sc);
                *(uint32_t*)&dst[(size_t)(row + 8) * HH + h] =
                    pack_h2((c[mi][ni][2] + b0) * sc, (c[mi][ni][3] + b1) * sc);
            }
        }
    }
}

// ---------------------------------------------------------------------------
// Kernel 2: fp16 mma flash attention — R11-exact (last passing version).
//  128-thr CTA (4 warps x 16 t-rows), 3-stage cp.async, 4 CTA/SM.
// ---------------------------------------------------------------------------
#define QSTRH 72                      // halves per smem row (Q and Vt)
#define STAGE_H (64 * QSTRH * 2)      // one stage: Q tile + V tile (halves)
#define Q_HOFF(buf) ((buf) * STAGE_H)
#define V_HOFF(buf) ((buf) * STAGE_H + 64 * QSTRH)
#define ATTN_SMEM_BYTES (3 * STAGE_H * 2)   // 55296

__global__ void __launch_bounds__(128, 4) attn_kernel()
{
    extern __shared__ __half smh[];
    const uint32_t sbase = smem_u32(smh);

    const int tid  = threadIdx.x;
    const int warp = tid >> 5;
    const int lane = tid & 31;
    const int g  = lane >> 2;
    const int t4 = lane & 3;
    const int b  = blockIdx.y;
    const int t0 = blockIdx.x * 64;
    const int z  = blockIdx.z;

    const __half* qb  = g_q  + (size_t)b * TT * HH;
    const __half* vtb = g_vt + (size_t)b * HH * TT;

    auto issue_tile = [&](int tile, int buf) {
        const int s0 = (z * 32 + tile) * 64;
        #pragma unroll
        for (int it = 0; it < 4; it++) {
            int i = tid + it * 128;          // 0..511
            int row = i >> 3, c8 = i & 7;
            cp_async16(sbase + (Q_HOFF(buf) + row * QSTRH + c8 * 8) * 2,
                       qb + (size_t)(s0 + row) * HH + c8 * 8);
            cp_async16(sbase + (V_HOFF(buf) + row * QSTRH + c8 * 8) * 2,
                       vtb + (size_t)row * TT + s0 + c8 * 8);
        }
        CP_COMMIT();
    };

    issue_tile(0, 0);
    issue_tile(1, 1);

    // --- K fragments (fp16) to registers: warp owns rows [warp*16, +16) ---
    uint32_t kf[4][4];
    {
        const __half* kbp = g_k + ((size_t)(b * TT) + t0 + warp * 16) * HH;
        #pragma unroll
        for (int kb = 0; kb < 4; kb++) {
            const int k0 = kb * 16 + 2 * t4;
            kf[kb][0] = *(const uint32_t*)&kbp[(size_t)g * HH + k0];
            kf[kb][1] = *(const uint32_t*)&kbp[(size_t)(g + 8) * HH + k0];
            kf[kb][2] = *(const uint32_t*)&kbp[(size_t)g * HH + k0 + 8];
            kf[kb][3] = *(const uint32_t*)&kbp[(size_t)(g + 8) * HH + k0 + 8];
        }
    }

    float o[8][4];
    #pragma unroll
    for (int nj = 0; nj < 8; nj++)
        #pragma unroll
        for (int e = 0; e < 4; e++) o[nj][e] = 0.0f;
    float ol[4] = {0.f, 0.f, 0.f, 0.f};           // ones-column: row sums
    const uint32_t ones = (g == 0) ? 0x3C003C00u : 0u;

    // ldmatrix per-lane byte offset
    const uint32_t lmlane =
        ((((lane >> 4) & 1) * 8 + (lane & 7)) * QSTRH) * 2 + ((lane >> 3) & 1) * 16;

    for (int tile = 0; tile < 32; tile++) {
        const int buf = tile % 3;
        if (tile >= 30) { CP_WAIT0(); } else { CP_WAIT1(); }
        __syncthreads();
        if (tile + 2 < 32) issue_tile(tile + 2, (tile + 2) % 3);

        const uint32_t qbase = sbase + Q_HOFF(buf) * 2 + lmlane;
        const uint32_t vbase = sbase + V_HOFF(buf) * 2 + lmlane;

        // ---- MMA1 + softmax in two ni-halves; P packs into MMA2 A-frags ----
        uint32_t pa[4][4];
        #pragma unroll
        for (int nh = 0; nh < 2; nh++) {
            float c[4][4];
            #pragma unroll
            for (int j = 0; j < 4; j++)
                #pragma unroll
                for (int e = 0; e < 4; e++) c[j][e] = 0.0f;

            #pragma unroll
            for (int kb = 0; kb < 4; kb++) {
                uint32_t q0[4], q1[4];
                ldmx4(q0, qbase + (2 * nh)     * (16 * QSTRH * 2) + kb * 32);
                ldmx4(q1, qbase + (2 * nh + 1) * (16 * QSTRH * 2) + kb * 32);
                mma_f16(c[0], kf[kb], q0[0], q0[1]);
                mma_f16(c[1], kf[kb], q0[2], q0[3]);
                mma_f16(c[2], kf[kb], q1[0], q1[1]);
                mma_f16(c[3], kf[kb], q1[2], q1[3]);
            }
            // pack logits to f16x2, then one MUFU per pair
            #pragma unroll
            for (int j = 0; j < 4; j++) {
                const int ni = nh * 4 + j;
                pa[ni >> 1][(ni & 1) * 2 + 0] = h2exp2(pack_h2(c[j][0], c[j][1]));
                pa[ni >> 1][(ni & 1) * 2 + 1] = h2exp2(pack_h2(c[j][2], c[j][3]));
            }
        }

        // ---- MMA2: O[16t x 64h] += P . V^T ; +ones column for row sums ----
        #pragma unroll
        for (int kb = 0; kb < 4; kb++) {
            #pragma unroll
            for (int m = 0; m < 4; m++) {
                uint32_t vf[4];
                ldmx4(vf, vbase + m * (16 * QSTRH * 2) + kb * 32);
                mma_f16(o[2 * m],     pa[kb], vf[0], vf[1]);
                mma_f16(o[2 * m + 1], pa[kb], vf[2], vf[3]);
            }
            mma_f16(ol, pa[kb], ones, ones);
        }
    }

    // ---- epilogue: row sums from ones-column; partial O to scratch ----
    const int row = t0 + warp * 16 + g;
    if (t4 == 0) {
        g_lpart[z * (BB * TT) + b * TT + row]     = ol[0];
        g_lpart[z * (BB * TT) + b * TT + row + 8] = ol[2];
    }
    float* ob = g_opart + (size_t)z * (BB * TT * HH) + (size_t)(b * TT + row) * HH;
    #pragma unroll
    for (int nj = 0; nj < 8; nj++) {
        const int col = nj * 8 + 2 * t4;
        *(float2*)&ob[col]          = make_float2(o[nj][0], o[nj][1]);
        *(float2*)&ob[8 * HH + col] = make_float2(o[nj][2], o[nj][3]);
    }
}

// ---------------------------------------------------------------------------
// Kernel 3: combine the two s-splits and normalize.
// ---------------------------------------------------------------------------
__global__ void __launch_bounds__(256) combine_kernel(float* __restrict__ out)
{
    const int i4 = blockIdx.x * 256 + threadIdx.x;
    const int row = i4 >> 4;
    const float inv = 1.0f / (g_lpart[row] + g_lpart[BB * TT + row]);
    const float4 a = ((const float4*)g_opart)[i4];
    const float4 c = ((const float4*)(g_opart + (size_t)BB * TT * HH))[i4];
    float4 r;
    r.x = (a.x + c.x) * inv;
    r.y = (a.y + c.y) * inv;
    r.z = (a.z + c.z) * inv;
    r.w = (a.w + c.w) * inv;
    ((float4*)out)[i4] = r;
}

// ---------------------------------------------------------------------------
extern "C" void kernel_launch(void* const* d_in, const int* in_sizes, int n_in,
                              void* d_out, int out_size)
{
    const float* x  = (const float*)d_in[0];
    const float* Wk = (const float*)d_in[1];
    const float* bk = (const float*)d_in[2];
    const float* Wq = (const float*)d_in[3];
    const float* bq = (const float*)d_in[4];
    const float* Wv = (const float*)d_in[5];
    const float* bv = (const float*)d_in[6];
    float* out = (float*)d_out;

    cudaFuncSetAttribute(qkv_mma_kernel, cudaFuncAttributeMaxDynamicSharedMemorySize,
                         QKV_SMEM_BYTES);
    cudaFuncSetAttribute(attn_kernel, cudaFuncAttributeMaxDynamicSharedMemorySize,
                         ATTN_SMEM_BYTES);

    wprep_kernel<<<192, 256>>>(Wk, bk, Wq, bq, Wv, bv);
    qkv_mma_kernel<<<(BB * TT) / 128, 512, QKV_SMEM_BYTES>>>(x);

    dim3 grid(TT / 64, BB, 2);
    attn_kernel<<<grid, 128, ATTN_SMEM_BYTES>>>();

    combine_kernel<<<(BB * TT * HH) / (4 * 256), 256>>>(out);
}